// round 14
// baseline (speedup 1.0000x reference)
#include <cuda_runtime.h>
#include <cuda_fp16.h>
#include <cstdint>

#define BATCH 8
#define NNODE 2048
#define DIM   128
#define NROWS (BATCH * NNODE)

__device__ float  g_u[NROWS], g_v[NROWS], g_p[NROWS], g_q[NROWS];
__device__ __half g_BH[NROWS * DIM];          // Wh fp16 rn [b][j][f]

// ---------------- helpers ----------------
__device__ __forceinline__ uint32_t smem_u32(const void* p) {
    uint32_t a;
    asm("{ .reg .u64 t; cvta.to.shared.u64 t, %1; cvt.u32.u64 %0, t; }" : "=r"(a) : "l"(p));
    return a;
}
__device__ __forceinline__ void ldsm_x4(uint32_t& r0, uint32_t& r1, uint32_t& r2, uint32_t& r3, uint32_t a) {
    asm volatile("ldmatrix.sync.aligned.m8n8.x4.shared.b16 {%0,%1,%2,%3}, [%4];"
                 : "=r"(r0), "=r"(r1), "=r"(r2), "=r"(r3) : "r"(a));
}
__device__ __forceinline__ void ldsm_x4t(uint32_t& r0, uint32_t& r1, uint32_t& r2, uint32_t& r3, uint32_t a) {
    asm volatile("ldmatrix.sync.aligned.m8n8.x4.trans.shared.b16 {%0,%1,%2,%3}, [%4];"
                 : "=r"(r0), "=r"(r1), "=r"(r2), "=r"(r3) : "r"(a));
}
__device__ __forceinline__ void mma16816(float* c, const uint32_t* a, uint32_t b0, uint32_t b1) {
    asm volatile(
        "mma.sync.aligned.m16n8k16.row.col.f32.f16.f16.f32 "
        "{%0,%1,%2,%3}, {%4,%5,%6,%7}, {%8,%9}, {%0,%1,%2,%3};"
        : "+f"(c[0]), "+f"(c[1]), "+f"(c[2]), "+f"(c[3])
        : "r"(a[0]), "r"(a[1]), "r"(a[2]), "r"(a[3]), "r"(b0), "r"(b1));
}
__device__ __forceinline__ void cp_async16(uint32_t dst, const void* src) {
    asm volatile("cp.async.cg.shared.global [%0], [%1], 16;" :: "r"(dst), "l"(src));
}
__device__ __forceinline__ uint32_t pack_f16x2(float lo, float hi) {   // lower<-lo, upper<-hi
    uint32_t r;
    asm("cvt.rn.f16x2.f32 %0, %1, %2;" : "=r"(r) : "f"(hi), "f"(lo));
    return r;
}
__device__ __forceinline__ void bar_sync(int id)   { asm volatile("bar.sync %0, 384;"   :: "r"(id) : "memory"); }
__device__ __forceinline__ void bar_arrive(int id) { asm volatile("bar.arrive %0, 384;" :: "r"(id) : "memory"); }

// ---------------------------------------------------------------------------
// K1: Wh = h @ W^T (hi/lo mma) + s,t + exp factors (known-good, ~12 us)
// ---------------------------------------------------------------------------
#define A_AH   0
#define A_AL   16384
#define A_BH   32768
#define A_BL   65536
#define A_SRED 98304
#define A_SMEM 100352

__global__ void __launch_bounds__(256, 2) gat_wh_st(
    const float* __restrict__ h, const float* __restrict__ W,
    const float* __restrict__ a)
{
    extern __shared__ char sm[];
    const uint32_t sb = smem_u32(sm);
    const int tid = threadIdx.x, lane = tid & 31, wid = tid >> 5;
    const int row0 = blockIdx.x * 64;

#pragma unroll
    for (int c = 0; c < 8; c++) {
        int idx = tid + 256 * c;
        int r = idx >> 5, fq = idx & 31;
        float4 w = *(const float4*)(h + (size_t)(row0 + r) * 128 + fq * 4);
        __half h0 = __float2half_rn(w.x), h1 = __float2half_rn(w.y);
        __half h2 = __float2half_rn(w.z), h3 = __float2half_rn(w.w);
        float l0 = w.x - __half2float(h0), l1 = w.y - __half2float(h1);
        float l2 = w.z - __half2float(h2), l3 = w.w - __half2float(h3);
        uint32_t sw = (uint32_t)(r * 256 + ((fq * 8) ^ ((r & 7) << 4)));
        __half2 hA = __halves2half2(h0, h1), hB = __halves2half2(h2, h3);
        *(uint2*)(sm + A_AH + sw) = make_uint2(*(uint32_t*)&hA, *(uint32_t*)&hB);
        *(uint2*)(sm + A_AL + sw) = make_uint2(pack_f16x2(l0, l1), pack_f16x2(l2, l3));
    }
#pragma unroll
    for (int c = 0; c < 16; c++) {
        int idx = tid + 256 * c;
        int o = idx >> 5, fq = idx & 31;
        float4 w = *(const float4*)(W + (size_t)o * 128 + fq * 4);
        __half h0 = __float2half_rn(w.x), h1 = __float2half_rn(w.y);
        __half h2 = __float2half_rn(w.z), h3 = __float2half_rn(w.w);
        float l0 = w.x - __half2float(h0), l1 = w.y - __half2float(h1);
        float l2 = w.z - __half2float(h2), l3 = w.w - __half2float(h3);
        uint32_t sw = (uint32_t)(o * 256 + ((fq * 8) ^ ((o & 7) << 4)));
        __half2 hA = __halves2half2(h0, h1), hB = __halves2half2(h2, h3);
        *(uint2*)(sm + A_BH + sw) = make_uint2(*(uint32_t*)&hA, *(uint32_t*)&hB);
        *(uint2*)(sm + A_BL + sw) = make_uint2(pack_f16x2(l0, l1), pack_f16x2(l2, l3));
    }
    __syncthreads();

    const int warpM = wid >> 2, warpN = wid & 3;
    const int l15 = lane & 15, l16 = lane >> 4;
    const uint32_t xorv = (uint32_t)((l15 & 7) << 4);

    float acc[2][4][4];
#pragma unroll
    for (int mt = 0; mt < 2; mt++)
#pragma unroll
        for (int nt = 0; nt < 4; nt++)
#pragma unroll
            for (int e = 0; e < 4; e++) acc[mt][nt][e] = 0.f;

    uint32_t aRow[2];
#pragma unroll
    for (int mt = 0; mt < 2; mt++)
        aRow[mt] = (uint32_t)((warpM * 32 + mt * 16 + l15) * 256);

    const int bR = (lane >> 4) * 8 + (lane & 7);
    const uint32_t bKoff = (uint32_t)(((lane >> 3) & 1) * 16);
    const uint32_t bXor = (uint32_t)((lane & 7) << 4);

#pragma unroll
    for (int kk = 0; kk < 8; kk++) {
        const uint32_t aCol = ((uint32_t)(kk * 32 + l16 * 16)) ^ xorv;
        uint32_t aH[2][4], aL[2][4];
#pragma unroll
        for (int mt = 0; mt < 2; mt++) {
            ldsm_x4(aH[mt][0], aH[mt][1], aH[mt][2], aH[mt][3], sb + A_AH + aRow[mt] + aCol);
            ldsm_x4(aL[mt][0], aL[mt][1], aL[mt][2], aL[mt][3], sb + A_AL + aRow[mt] + aCol);
        }
        uint32_t bH[2][4], bL[2][4];
#pragma unroll
        for (int ng = 0; ng < 2; ng++) {
            int n = warpN * 32 + ng * 16 + bR;
            uint32_t addr = (uint32_t)(n * 256) + (((uint32_t)(kk * 32) + bKoff) ^ bXor);
            ldsm_x4(bH[ng][0], bH[ng][1], bH[ng][2], bH[ng][3], sb + A_BH + addr);
            ldsm_x4(bL[ng][0], bL[ng][1], bL[ng][2], bL[ng][3], sb + A_BL + addr);
        }
#pragma unroll
        for (int mt = 0; mt < 2; mt++)
#pragma unroll
            for (int nt = 0; nt < 4; nt++) {
                const int g = nt >> 1, hh = (nt & 1) * 2;
                mma16816(acc[mt][nt], aH[mt], bH[g][hh], bH[g][hh + 1]);
                mma16816(acc[mt][nt], aH[mt], bL[g][hh], bL[g][hh + 1]);
                mma16816(acc[mt][nt], aL[mt], bH[g][hh], bH[g][hh + 1]);
            }
    }

#pragma unroll
    for (int mt = 0; mt < 2; mt++) {
        const int r0 = row0 + warpM * 32 + mt * 16 + (lane >> 2);
        const int r1 = r0 + 8;
#pragma unroll
        for (int nt = 0; nt < 4; nt++) {
            const int c0 = warpN * 32 + nt * 8 + (lane & 3) * 2;
            __half h0 = __float2half_rn(acc[mt][nt][0]), h1 = __float2half_rn(acc[mt][nt][1]);
            __half h2 = __float2half_rn(acc[mt][nt][2]), h3 = __float2half_rn(acc[mt][nt][3]);
            __half2 p0 = __halves2half2(h0, h1), p1 = __halves2half2(h2, h3);
            *(uint32_t*)(g_BH + (size_t)r0 * 128 + c0) = *(uint32_t*)&p0;
            *(uint32_t*)(g_BH + (size_t)r1 * 128 + c0) = *(uint32_t*)&p1;
        }
    }

    float ps[2][2] = {{0.f,0.f},{0.f,0.f}}, pt[2][2] = {{0.f,0.f},{0.f,0.f}};
#pragma unroll
    for (int mt = 0; mt < 2; mt++)
#pragma unroll
        for (int nt = 0; nt < 4; nt++) {
            const int c0 = warpN * 32 + nt * 8 + (lane & 3) * 2;
            float2 av = *(const float2*)(a + c0);
            float2 dv = *(const float2*)(a + 128 + c0);
            ps[mt][0] += acc[mt][nt][0] * av.x + acc[mt][nt][1] * av.y;
            ps[mt][1] += acc[mt][nt][2] * av.x + acc[mt][nt][3] * av.y;
            pt[mt][0] += acc[mt][nt][0] * dv.x + acc[mt][nt][1] * dv.y;
            pt[mt][1] += acc[mt][nt][2] * dv.x + acc[mt][nt][3] * dv.y;
        }
#pragma unroll
    for (int o = 1; o < 4; o <<= 1) {
#pragma unroll
        for (int mt = 0; mt < 2; mt++) {
            ps[mt][0] += __shfl_xor_sync(0xFFFFFFFFu, ps[mt][0], o);
            ps[mt][1] += __shfl_xor_sync(0xFFFFFFFFu, ps[mt][1], o);
            pt[mt][0] += __shfl_xor_sync(0xFFFFFFFFu, pt[mt][0], o);
            pt[mt][1] += __shfl_xor_sync(0xFFFFFFFFu, pt[mt][1], o);
        }
    }
    float* sredS = (float*)(sm + A_SRED);
    float* sredT = (float*)(sm + A_SRED + 1024);
    if ((lane & 3) == 0) {
#pragma unroll
        for (int mt = 0; mt < 2; mt++) {
            int rl = warpM * 32 + mt * 16 + (lane >> 2);
            sredS[rl * 4 + warpN] = ps[mt][0];
            sredS[(rl + 8) * 4 + warpN] = ps[mt][1];
            sredT[rl * 4 + warpN] = pt[mt][0];
            sredT[(rl + 8) * 4 + warpN] = pt[mt][1];
        }
    }
    __syncthreads();
    if (tid < 64) {
        float s = sredS[tid*4] + sredS[tid*4+1] + sredS[tid*4+2] + sredS[tid*4+3];
        float t = sredT[tid*4] + sredT[tid*4+1] + sredT[tid*4+2] + sredT[tid*4+3];
        int row = row0 + tid;
        g_u[row] = __expf(s);   g_p[row] = __expf(0.2f * s);
        g_v[row] = __expf(t);   g_q[row] = __expf(0.2f * t);
    }
}

// ---------------------------------------------------------------------------
// K4: fused, WARP-SPECIALIZED. 384 thr: warps 0-7 consumers (pure mma),
//     warps 8-11 producers (adj LDG, P construct, B cp.async, Z).
//     M=64, TK=64, double-buffered P/B, named-barrier handshake.
// ---------------------------------------------------------------------------
#define TK 64
#define NT (NNODE / TK)
#define F_P(bu)  ((bu) * 8192)              // P  64x64 fp16 (128B rows)
#define F_B(bu)  (16384 + (bu) * 16384)     // Wh 64x128 fp16 (256B rows)
#define F_ZR     49152                       // 64 f32
#define F_ZI     49408                       // 64 f32
#define F_SMEM   49664
// barrier ids: full = 1+buf, empty = 3+buf

__global__ void __launch_bounds__(384, 2) gat_fused(
    const int* __restrict__ adj, float* __restrict__ out)
{
    extern __shared__ char sm[];
    const uint32_t sb = smem_u32(sm);
    const int tid = threadIdx.x, lane = tid & 31, wid = tid >> 5;
    const int b = blockIdx.y, i0 = blockIdx.x * 64;

    float* zr = (float*)(sm + F_ZR);
    float* zi = (float*)(sm + F_ZI);

    if (wid >= 8) {
        // ================= PRODUCER (warps 8..11, 128 threads) =================
        const int tid2 = tid - 256;                // 0..127
        const int ptx = tid2 & 15;                 // j group of 4
        const int prow = tid2 >> 4;                // 0..7

        const __half* BHg  = g_BH + (size_t)b * NNODE * DIM;
        const int*    adjB = adj + ((size_t)(b * NNODE + i0)) * NNODE;
        const float*  vB   = g_v + b * NNODE;
        const float*  qB   = g_q + b * NNODE;

        float u_r[8], p_r[8];
#pragma unroll
        for (int m = 0; m < 8; m++) {
            int il = prow + 8 * m;
            u_r[m] = g_u[b * NNODE + i0 + il];
            p_r[m] = g_p[b * NNODE + i0 + il];
        }
        float zacc[8] = {0.f,0.f,0.f,0.f,0.f,0.f,0.f,0.f};

        for (int kt = 0; kt < NT; ++kt) {
            const int buf = kt & 1;
            if (kt >= 2) bar_sync(3 + buf);        // wait consumers done with buf

            // issue B(kt): 16KB via 128 threads x 8 cp.async
            const int j0 = kt * TK;
#pragma unroll
            for (int c = 0; c < 8; c++) {
                int idx = tid2 + 128 * c;
                int row = idx >> 4, col = idx & 15;
                uint32_t sw = (uint32_t)(row * 256 + ((col * 16) ^ ((row & 7) << 4)));
                cp_async16(sb + F_B(buf) + sw, BHg + (size_t)(j0 + row) * DIM + col * 8);
            }
            asm volatile("cp.async.commit_group;" ::: "memory");

            // construct P(kt): 8 rows/thread, 4 j/thread, two 4-row batches
            float4 v4 = *(const float4*)(vB + j0 + 4 * ptx);
            float4 q4 = *(const float4*)(qB + j0 + 4 * ptx);
            char* P = sm + F_P(buf);
#pragma unroll
            for (int hb = 0; hb < 2; hb++) {
                int4 a4[4];
#pragma unroll
                for (int m = 0; m < 4; m++)
                    a4[m] = *((const int4*)(adjB + (size_t)(prow + 8 * (hb * 4 + m)) * NNODE + j0) + ptx);
#pragma unroll
                for (int m = 0; m < 4; m++) {
                    const int mi = hb * 4 + m;
                    const int row = prow + 8 * mi;
                    const float u = u_r[mi], p = p_r[mi];
                    uint32_t w0 = __float_as_uint(fmaxf(u * v4.x, p * q4.x)) & (uint32_t)(-a4[m].x);
                    uint32_t w1 = __float_as_uint(fmaxf(u * v4.y, p * q4.y)) & (uint32_t)(-a4[m].y);
                    uint32_t w2 = __float_as_uint(fmaxf(u * v4.z, p * q4.z)) & (uint32_t)(-a4[m].z);
                    uint32_t w3 = __float_as_uint(fmaxf(u * v4.w, p * q4.w)) & (uint32_t)(-a4[m].w);
                    float f0 = __uint_as_float(w0), f1 = __uint_as_float(w1);
                    float f2 = __uint_as_float(w2), f3 = __uint_as_float(w3);
                    zacc[mi] += (f0 + f1) + (f2 + f3);
                    *(uint2*)(P + row * 128 + ((ptx * 8) ^ ((row & 7) << 4))) =
                        make_uint2(pack_f16x2(f0, f1), pack_f16x2(f2, f3));
                }
            }
            asm volatile("cp.async.wait_group 0;" ::: "memory");
            bar_arrive(1 + buf);                   // publish full(buf)
        }

        // Z: reduce over the 16 ptx lanes sharing each row
#pragma unroll
        for (int m = 0; m < 8; m++) {
            float z = zacc[m];
#pragma unroll
            for (int o = 1; o < 16; o <<= 1)
                z += __shfl_xor_sync(0xFFFFFFFFu, z, o);
            if ((lane & 15) == 0) zr[prow + 8 * m] = z;
        }
        __syncthreads();   // all 384: zr ready
        if (tid2 < 64) {
            float z = zr[tid2];
            zi[tid2] = (z > 0.f) ? (1.f / z) : 0.f;
        }
        __syncthreads();   // zi ready
    } else {
        // ================= CONSUMER (warps 0..7, 256 threads) =================
        const int warpM = wid >> 2, warpN = wid & 3;
        const int l15 = lane & 15, l16 = lane >> 4;
        const uint32_t xorv = (uint32_t)((l15 & 7) << 4);
        uint32_t aRow[2];
#pragma unroll
        for (int mt = 0; mt < 2; mt++)
            aRow[mt] = (uint32_t)((warpM * 32 + mt * 16 + l15) * 128);
        uint32_t bCol[2];
#pragma unroll
        for (int ng = 0; ng < 2; ng++)
            bCol[ng] = ((uint32_t)((warpN * 32 + ng * 16 + l16 * 8) * 2)) ^ xorv;
        const uint32_t bRow0 = (uint32_t)(l15 * 256);

        float acc[2][4][4];
#pragma unroll
        for (int mt = 0; mt < 2; mt++)
#pragma unroll
            for (int nt = 0; nt < 4; nt++)
#pragma unroll
                for (int e = 0; e < 4; e++) acc[mt][nt][e] = 0.f;

        for (int kt = 0; kt < NT; ++kt) {
            const int buf = kt & 1;
            bar_sync(1 + buf);                     // wait full(buf)
            const uint32_t Pb = sb + F_P(buf), Bb = sb + F_B(buf);
#pragma unroll
            for (int kk = 0; kk < 4; ++kk) {
                const uint32_t aCol = ((uint32_t)(kk * 32 + l16 * 16)) ^ xorv;
                uint32_t aH[2][4];
#pragma unroll
                for (int mt = 0; mt < 2; mt++)
                    ldsm_x4(aH[mt][0], aH[mt][1], aH[mt][2], aH[mt][3], Pb + aRow[mt] + aCol);
                const uint32_t bRow = bRow0 + (uint32_t)(kk * 4096);
                uint32_t bH[2][4];
#pragma unroll
                for (int ng = 0; ng < 2; ng++)
                    ldsm_x4t(bH[ng][0], bH[ng][1], bH[ng][2], bH[ng][3], Bb + bRow + bCol[ng]);
#pragma unroll
                for (int mt = 0; mt < 2; mt++)
#pragma unroll
                    for (int nt = 0; nt < 4; nt++) {
                        const int g = nt >> 1, hh = (nt & 1) * 2;
                        mma16816(acc[mt][nt], aH[mt], bH[g][hh], bH[g][hh + 1]);
                    }
            }
            if (kt + 2 < NT) bar_arrive(3 + buf);  // release empty(buf)
        }

        __syncthreads();   // producers write zr
        __syncthreads();   // zi ready

        float* outB = out + ((size_t)(b * NNODE + i0)) * DIM;
#pragma unroll
        for (int mt = 0; mt < 2; mt++) {
            const int r0 = warpM * 32 + mt * 16 + (lane >> 2);
            const int r1 = r0 + 8;
            const float z0 = zi[r0], z1 = zi[r1];
#pragma unroll
            for (int nt = 0; nt < 4; nt++) {
                const int c0 = warpN * 32 + nt * 8 + (lane & 3) * 2;
                *(float2*)(outB + (size_t)r0 * DIM + c0) =
                    make_float2(acc[mt][nt][0] * z0, acc[mt][nt][1] * z0);
                *(float2*)(outB + (size_t)r1 * DIM + c0) =
                    make_float2(acc[mt][nt][2] * z1, acc[mt][nt][3] * z1);
            }
        }
    }
}

// ---------------------------------------------------------------------------
extern "C" void kernel_launch(void* const* d_in, const int* in_sizes, int n_in,
                              void* d_out, int out_size)
{
    const float* h   = (const float*)d_in[0];
    const int*   adj = (const int*)  d_in[1];
    const float* W   = (const float*)d_in[2];
    const float* a   = (const float*)d_in[3];
    float*       out = (float*)d_out;

    static int attr_set = 0;
    if (!attr_set) {
        cudaFuncSetAttribute(gat_wh_st, cudaFuncAttributeMaxDynamicSharedMemorySize, A_SMEM);
        cudaFuncSetAttribute(gat_fused, cudaFuncAttributeMaxDynamicSharedMemorySize, F_SMEM);
        attr_set = 1;
    }

    gat_wh_st<<<NROWS / 64, 256, A_SMEM>>>(h, W, a);
    gat_fused<<<dim3(NNODE / 64, BATCH), 384, F_SMEM>>>(adj, out);
}

// round 15
// speedup vs baseline: 2.2539x; 2.2539x over previous
#include <cuda_runtime.h>
#include <cuda_fp16.h>
#include <cstdint>

#define BATCH 8
#define NNODE 2048
#define DIM   128
#define NROWS (BATCH * NNODE)

__device__ float  g_u[NROWS], g_v[NROWS], g_p[NROWS], g_q[NROWS];
__device__ __half g_BH[NROWS * DIM];     // Wh fp16 rn [b][j][f]

// ---------------- helpers ----------------
__device__ __forceinline__ uint32_t smem_u32(const void* p) {
    uint32_t a;
    asm("{ .reg .u64 t; cvta.to.shared.u64 t, %1; cvt.u32.u64 %0, t; }" : "=r"(a) : "l"(p));
    return a;
}
__device__ __forceinline__ void ldsm_x4(uint32_t& r0, uint32_t& r1, uint32_t& r2, uint32_t& r3, uint32_t a) {
    asm volatile("ldmatrix.sync.aligned.m8n8.x4.shared.b16 {%0,%1,%2,%3}, [%4];"
                 : "=r"(r0), "=r"(r1), "=r"(r2), "=r"(r3) : "r"(a));
}
__device__ __forceinline__ void ldsm_x4t(uint32_t& r0, uint32_t& r1, uint32_t& r2, uint32_t& r3, uint32_t a) {
    asm volatile("ldmatrix.sync.aligned.m8n8.x4.trans.shared.b16 {%0,%1,%2,%3}, [%4];"
                 : "=r"(r0), "=r"(r1), "=r"(r2), "=r"(r3) : "r"(a));
}
__device__ __forceinline__ void mma16816(float* c, const uint32_t* a, uint32_t b0, uint32_t b1) {
    asm volatile(
        "mma.sync.aligned.m16n8k16.row.col.f32.f16.f16.f32 "
        "{%0,%1,%2,%3}, {%4,%5,%6,%7}, {%8,%9}, {%0,%1,%2,%3};"
        : "+f"(c[0]), "+f"(c[1]), "+f"(c[2]), "+f"(c[3])
        : "r"(a[0]), "r"(a[1]), "r"(a[2]), "r"(a[3]), "r"(b0), "r"(b1));
}
__device__ __forceinline__ void cp_async16(uint32_t dst, const void* src) {
    asm volatile("cp.async.cg.shared.global [%0], [%1], 16;" :: "r"(dst), "l"(src));
}
__device__ __forceinline__ uint32_t pack_f16x2(float lo, float hi) {   // lower<-lo, upper<-hi
    uint32_t r;
    asm("cvt.rn.f16x2.f32 %0, %1, %2;" : "=r"(r) : "f"(hi), "f"(lo));
    return r;
}

// ---------------------------------------------------------------------------
// K1: Wh = h @ W^T (hi/lo mma) + s,t + exp factors. W converted in-kernel,
//     stored native row-major (B via non-trans ldmatrix). 256 CTAs x 64 rows.
//     Measured 12.2-12.3 us in R10/R12.
// ---------------------------------------------------------------------------
#define A_AH   0
#define A_AL   16384
#define A_BH   32768
#define A_BL   65536
#define A_SRED 98304
#define A_SMEM 100352

__global__ void __launch_bounds__(256, 2) gat_wh_st(
    const float* __restrict__ h, const float* __restrict__ W,
    const float* __restrict__ a)
{
    extern __shared__ char sm[];
    const uint32_t sb = smem_u32(sm);
    const int tid = threadIdx.x, lane = tid & 31, wid = tid >> 5;
    const int row0 = blockIdx.x * 64;

    // h tile (64 x 128 f32) -> hi/lo fp16 smem (256B rows, xor swizzle)
#pragma unroll
    for (int c = 0; c < 8; c++) {
        int idx = tid + 256 * c;
        int r = idx >> 5, fq = idx & 31;
        float4 w = *(const float4*)(h + (size_t)(row0 + r) * 128 + fq * 4);
        __half h0 = __float2half_rn(w.x), h1 = __float2half_rn(w.y);
        __half h2 = __float2half_rn(w.z), h3 = __float2half_rn(w.w);
        float l0 = w.x - __half2float(h0), l1 = w.y - __half2float(h1);
        float l2 = w.z - __half2float(h2), l3 = w.w - __half2float(h3);
        uint32_t sw = (uint32_t)(r * 256 + ((fq * 8) ^ ((r & 7) << 4)));
        __half2 hA = __halves2half2(h0, h1), hB = __halves2half2(h2, h3);
        *(uint2*)(sm + A_AH + sw) = make_uint2(*(uint32_t*)&hA, *(uint32_t*)&hB);
        *(uint2*)(sm + A_AL + sw) = make_uint2(pack_f16x2(l0, l1), pack_f16x2(l2, l3));
    }

    // W (128 x 128 f32) -> hi/lo fp16 smem, NATIVE row-major layout
#pragma unroll
    for (int c = 0; c < 16; c++) {
        int idx = tid + 256 * c;
        int o = idx >> 5, fq = idx & 31;
        float4 w = *(const float4*)(W + (size_t)o * 128 + fq * 4);
        __half h0 = __float2half_rn(w.x), h1 = __float2half_rn(w.y);
        __half h2 = __float2half_rn(w.z), h3 = __float2half_rn(w.w);
        float l0 = w.x - __half2float(h0), l1 = w.y - __half2float(h1);
        float l2 = w.z - __half2float(h2), l3 = w.w - __half2float(h3);
        uint32_t sw = (uint32_t)(o * 256 + ((fq * 8) ^ ((o & 7) << 4)));
        __half2 hA = __halves2half2(h0, h1), hB = __halves2half2(h2, h3);
        *(uint2*)(sm + A_BH + sw) = make_uint2(*(uint32_t*)&hA, *(uint32_t*)&hB);
        *(uint2*)(sm + A_BL + sw) = make_uint2(pack_f16x2(l0, l1), pack_f16x2(l2, l3));
    }
    __syncthreads();

    const int warpM = wid >> 2, warpN = wid & 3;     // 2 x 4
    const int l15 = lane & 15, l16 = lane >> 4;
    const uint32_t xorv = (uint32_t)((l15 & 7) << 4);

    float acc[2][4][4];
#pragma unroll
    for (int mt = 0; mt < 2; mt++)
#pragma unroll
        for (int nt = 0; nt < 4; nt++)
#pragma unroll
            for (int e = 0; e < 4; e++) acc[mt][nt][e] = 0.f;

    uint32_t aRow[2];
#pragma unroll
    for (int mt = 0; mt < 2; mt++)
        aRow[mt] = (uint32_t)((warpM * 32 + mt * 16 + l15) * 256);

    // non-trans B lane addressing: row = n, col = k
    const int bR = (lane >> 4) * 8 + (lane & 7);
    const uint32_t bKoff = (uint32_t)(((lane >> 3) & 1) * 16);
    const uint32_t bXor = (uint32_t)((lane & 7) << 4);

#pragma unroll
    for (int kk = 0; kk < 8; kk++) {
        const uint32_t aCol = ((uint32_t)(kk * 32 + l16 * 16)) ^ xorv;
        uint32_t aH[2][4], aL[2][4];
#pragma unroll
        for (int mt = 0; mt < 2; mt++) {
            ldsm_x4(aH[mt][0], aH[mt][1], aH[mt][2], aH[mt][3], sb + A_AH + aRow[mt] + aCol);
            ldsm_x4(aL[mt][0], aL[mt][1], aL[mt][2], aL[mt][3], sb + A_AL + aRow[mt] + aCol);
        }
        uint32_t bH[2][4], bL[2][4];
#pragma unroll
        for (int ng = 0; ng < 2; ng++) {
            int n = warpN * 32 + ng * 16 + bR;
            uint32_t addr = (uint32_t)(n * 256) + (((uint32_t)(kk * 32) + bKoff) ^ bXor);
            ldsm_x4(bH[ng][0], bH[ng][1], bH[ng][2], bH[ng][3], sb + A_BH + addr);
            ldsm_x4(bL[ng][0], bL[ng][1], bL[ng][2], bL[ng][3], sb + A_BL + addr);
        }
#pragma unroll
        for (int mt = 0; mt < 2; mt++)
#pragma unroll
            for (int nt = 0; nt < 4; nt++) {
                const int g = nt >> 1, hh = (nt & 1) * 2;
                mma16816(acc[mt][nt], aH[mt], bH[g][hh], bH[g][hh + 1]);
                mma16816(acc[mt][nt], aH[mt], bL[g][hh], bL[g][hh + 1]);
                mma16816(acc[mt][nt], aL[mt], bH[g][hh], bH[g][hh + 1]);
            }
    }

    // store Wh fp16 rn
#pragma unroll
    for (int mt = 0; mt < 2; mt++) {
        const int r0 = row0 + warpM * 32 + mt * 16 + (lane >> 2);
        const int r1 = r0 + 8;
#pragma unroll
        for (int nt = 0; nt < 4; nt++) {
            const int c0 = warpN * 32 + nt * 8 + (lane & 3) * 2;
            __half h0 = __float2half_rn(acc[mt][nt][0]), h1 = __float2half_rn(acc[mt][nt][1]);
            __half h2 = __float2half_rn(acc[mt][nt][2]), h3 = __float2half_rn(acc[mt][nt][3]);
            __half2 p0 = __halves2half2(h0, h1), p1 = __halves2half2(h2, h3);
            *(uint32_t*)(g_BH + (size_t)r0 * 128 + c0) = *(uint32_t*)&p0;
            *(uint32_t*)(g_BH + (size_t)r1 * 128 + c0) = *(uint32_t*)&p1;
        }
    }

    // s,t from exact accumulators
    float ps[2][2] = {{0.f,0.f},{0.f,0.f}}, pt[2][2] = {{0.f,0.f},{0.f,0.f}};
#pragma unroll
    for (int mt = 0; mt < 2; mt++)
#pragma unroll
        for (int nt = 0; nt < 4; nt++) {
            const int c0 = warpN * 32 + nt * 8 + (lane & 3) * 2;
            float2 av = *(const float2*)(a + c0);
            float2 dv = *(const float2*)(a + 128 + c0);
            ps[mt][0] += acc[mt][nt][0] * av.x + acc[mt][nt][1] * av.y;
            ps[mt][1] += acc[mt][nt][2] * av.x + acc[mt][nt][3] * av.y;
            pt[mt][0] += acc[mt][nt][0] * dv.x + acc[mt][nt][1] * dv.y;
            pt[mt][1] += acc[mt][nt][2] * dv.x + acc[mt][nt][3] * dv.y;
        }
#pragma unroll
    for (int o = 1; o < 4; o <<= 1) {
#pragma unroll
        for (int mt = 0; mt < 2; mt++) {
            ps[mt][0] += __shfl_xor_sync(0xFFFFFFFFu, ps[mt][0], o);
            ps[mt][1] += __shfl_xor_sync(0xFFFFFFFFu, ps[mt][1], o);
            pt[mt][0] += __shfl_xor_sync(0xFFFFFFFFu, pt[mt][0], o);
            pt[mt][1] += __shfl_xor_sync(0xFFFFFFFFu, pt[mt][1], o);
        }
    }
    float* sredS = (float*)(sm + A_SRED);
    float* sredT = (float*)(sm + A_SRED + 1024);
    if ((lane & 3) == 0) {
#pragma unroll
        for (int mt = 0; mt < 2; mt++) {
            int rl = warpM * 32 + mt * 16 + (lane >> 2);
            sredS[rl * 4 + warpN] = ps[mt][0];
            sredS[(rl + 8) * 4 + warpN] = ps[mt][1];
            sredT[rl * 4 + warpN] = pt[mt][0];
            sredT[(rl + 8) * 4 + warpN] = pt[mt][1];
        }
    }
    __syncthreads();
    if (tid < 64) {
        float s = sredS[tid*4] + sredS[tid*4+1] + sredS[tid*4+2] + sredS[tid*4+3];
        float t = sredT[tid*4] + sredT[tid*4+1] + sredT[tid*4+2] + sredT[tid*4+3];
        int row = row0 + tid;
        g_u[row] = __expf(s);   g_p[row] = __expf(0.2f * s);
        g_v[row] = __expf(t);   g_q[row] = __expf(0.2f * t);
    }
}

// ---------------------------------------------------------------------------
// K4: fused — EXACT R7 structure (best measured: 46.2 us) with ONE change:
//     v,q staged to smem in the prologue; construct reads LDS not gmem.
//     M=64, TK=64, 256 thr, 2 CTAs/SM, adj gmem->regs, B double-buffered.
// ---------------------------------------------------------------------------
#define TK 64
#define F_P(bu)  ((bu) * 8192)              // P  64x64 fp16 (128B rows)
#define F_B(bu)  (16384 + (bu) * 16384)     // Wh 64x128 fp16 (256B rows)
#define F_V      49152                       // v[2048] f32
#define F_Q      57344                       // q[2048] f32
#define F_ZR     65536
#define F_ZI     65792
#define F_SMEM   66048

__global__ void __launch_bounds__(256, 2) gat_fused(
    const int* __restrict__ adj, float* __restrict__ out)
{
    extern __shared__ char sm[];
    const uint32_t sb = smem_u32(sm);
    const int tid = threadIdx.x, lane = tid & 31, wid = tid >> 5;
    const int b = blockIdx.y, i0 = blockIdx.x * 64;
    const int tx = tid & 15, ty = tid >> 4;     // ty: 0..15

    const __half* BHg = g_BH + (size_t)b * NNODE * DIM;

    float u_r[4], p_r[4];
    const int* adjRow[4];
#pragma unroll
    for (int m = 0; m < 4; m++) {
        int il = ty + 16 * m;                    // rows 0..63
        u_r[m] = g_u[b * NNODE + i0 + il];
        p_r[m] = g_p[b * NNODE + i0 + il];
        adjRow[m] = adj + ((size_t)(b * NNODE + i0 + il)) * NNODE + 4 * tx;
    }

    // prologue: v,q (16KB) + B(0) via cp.async
#pragma unroll
    for (int c = 0; c < 2; c++) {
        int idx = tid + 256 * c;                 // 0..511
        cp_async16(sb + F_V + idx * 16, g_v + b * NNODE + idx * 4);
        cp_async16(sb + F_Q + idx * 16, g_q + b * NNODE + idx * 4);
    }
#pragma unroll
    for (int c2 = 0; c2 < 4; c2++) {
        int c = tid + 256 * c2;
        int row = c >> 4, col = c & 15;
        uint32_t sw = (uint32_t)(row * 256 + ((col * 16) ^ ((row & 7) << 4)));
        cp_async16(sb + F_B(0) + sw, BHg + (size_t)row * DIM + col * 8);
    }
    asm volatile("cp.async.commit_group;" ::: "memory");
    asm volatile("cp.async.wait_group 0;" ::: "memory");
    __syncthreads();

    float zacc[4] = {0.f, 0.f, 0.f, 0.f};

    // construct P(0): adj direct from gmem, v/q from smem
    {
        float4 v4 = *(const float4*)(sm + F_V + 16 * tx);
        float4 q4 = *(const float4*)(sm + F_Q + 16 * tx);
        char* P = sm + F_P(0);
#pragma unroll
        for (int m = 0; m < 4; m++) {
            const int row = ty + 16 * m;
            int4 a4 = *(const int4*)adjRow[m];
            const float u = u_r[m], p = p_r[m];
            uint32_t w0 = __float_as_uint(fmaxf(u * v4.x, p * q4.x)) & (uint32_t)(-a4.x);
            uint32_t w1 = __float_as_uint(fmaxf(u * v4.y, p * q4.y)) & (uint32_t)(-a4.y);
            uint32_t w2 = __float_as_uint(fmaxf(u * v4.z, p * q4.z)) & (uint32_t)(-a4.z);
            uint32_t w3 = __float_as_uint(fmaxf(u * v4.w, p * q4.w)) & (uint32_t)(-a4.w);
            float f0 = __uint_as_float(w0), f1 = __uint_as_float(w1);
            float f2 = __uint_as_float(w2), f3 = __uint_as_float(w3);
            zacc[m] += (f0 + f1) + (f2 + f3);
            *(uint2*)(P + row * 128 + ((tx * 8) ^ ((row & 7) << 4))) =
                make_uint2(pack_f16x2(f0, f1), pack_f16x2(f2, f3));
        }
    }

    // adj(1) prefetch into regs
    int4 aN[4];
#pragma unroll
    for (int m = 0; m < 4; m++) aN[m] = *(const int4*)(adjRow[m] + TK);

    float acc[2][4][4];
#pragma unroll
    for (int mt = 0; mt < 2; mt++)
#pragma unroll
        for (int nt = 0; nt < 4; nt++)
#pragma unroll
            for (int e = 0; e < 4; e++) acc[mt][nt][e] = 0.f;

    const int warpM = wid >> 2, warpN = wid & 3;   // 2 x 4
    const int l15 = lane & 15, l16 = lane >> 4;
    const uint32_t xorv = (uint32_t)((l15 & 7) << 4);
    uint32_t aRow[2];
#pragma unroll
    for (int mt = 0; mt < 2; mt++)
        aRow[mt] = (uint32_t)((warpM * 32 + mt * 16 + l15) * 128);
    uint32_t bCol[2];
#pragma unroll
    for (int ng = 0; ng < 2; ng++)
        bCol[ng] = ((uint32_t)((warpN * 32 + ng * 16 + l16 * 8) * 2)) ^ xorv;
    const uint32_t bRow0 = (uint32_t)(l15 * 256);

    __syncthreads();

    for (int kt = 0; kt < NNODE / TK; ++kt) {
        const int cb = kt & 1, pb = cb ^ 1;

        // stream B(kt+1)
        if (kt < 31) {
            const int j1 = (kt + 1) * TK;
#pragma unroll
            for (int c2 = 0; c2 < 4; c2++) {
                int c = tid + 256 * c2;
                int row = c >> 4, col = c & 15;
                uint32_t sw = (uint32_t)(row * 256 + ((col * 16) ^ ((row & 7) << 4)));
                cp_async16(sb + F_B(pb) + sw, BHg + (size_t)(j1 + row) * DIM + col * 8);
            }
        }
        asm volatile("cp.async.commit_group;" ::: "memory");

        const uint32_t Pb = sb + F_P(cb), Bb = sb + F_B(cb);
#pragma unroll
        for (int kk = 0; kk < 4; ++kk) {
            const uint32_t aCol = ((uint32_t)(kk * 32 + l16 * 16)) ^ xorv;
            uint32_t aH[2][4];
#pragma unroll
            for (int mt = 0; mt < 2; mt++)
                ldsm_x4(aH[mt][0], aH[mt][1], aH[mt][2], aH[mt][3], Pb + aRow[mt] + aCol);
            const uint32_t bRow = bRow0 + (uint32_t)(kk * 4096);
            uint32_t bH[2][4];
#pragma unroll
            for (int ng = 0; ng < 2; ng++)
                ldsm_x4t(bH[ng][0], bH[ng][1], bH[ng][2], bH[ng][3], Bb + bRow + bCol[ng]);
#pragma unroll
            for (int mt = 0; mt < 2; mt++)
#pragma unroll
                for (int nt = 0; nt < 4; nt++) {
                    const int g = nt >> 1, hh = (nt & 1) * 2;
                    mma16816(acc[mt][nt], aH[mt], bH[g][hh], bH[g][hh + 1]);
                }

            if (kk == 0 && kt < 31) {
                // construct P(kt+1): v/q from smem (29-cyc LDS, no gmem dep)
                const int jn = (kt + 1) * TK + 4 * tx;
                float4 v4 = *(const float4*)(sm + F_V + jn * 4);
                float4 q4 = *(const float4*)(sm + F_Q + jn * 4);
                char* P = sm + F_P(pb);
#pragma unroll
                for (int m = 0; m < 4; m++) {
                    const int row = ty + 16 * m;
                    const int4 a4 = aN[m];
                    const float u = u_r[m], p = p_r[m];
                    uint32_t w0 = __float_as_uint(fmaxf(u * v4.x, p * q4.x)) & (uint32_t)(-a4.x);
                    uint32_t w1 = __float_as_uint(fmaxf(u * v4.y, p * q4.y)) & (uint32_t)(-a4.y);
                    uint32_t w2 = __float_as_uint(fmaxf(u * v4.z, p * q4.z)) & (uint32_t)(-a4.z);
                    uint32_t w3 = __float_as_uint(fmaxf(u * v4.w, p * q4.w)) & (uint32_t)(-a4.w);
                    float f0 = __uint_as_float(w0), f1 = __uint_as_float(w1);
                    float f2 = __uint_as_float(w2), f3 = __uint_as_float(w3);
                    zacc[m] += (f0 + f1) + (f2 + f3);
                    *(uint2*)(P + row * 128 + ((tx * 8) ^ ((row & 7) << 4))) =
                        make_uint2(pack_f16x2(f0, f1), pack_f16x2(f2, f3));
                }
            }
            if (kk == 2 && kt < 30) {
                // prefetch adj(kt+2) into regs
                const int j2 = (kt + 2) * TK;
#pragma unroll
                for (int m = 0; m < 4; m++)
                    aN[m] = *(const int4*)(adjRow[m] + j2);
            }
        }
        asm volatile("cp.async.wait_group 0;" ::: "memory");
        __syncthreads();
    }

    // Z reduction and normalize
    float* zr = (float*)(sm + F_ZR);
    float* zi = (float*)(sm + F_ZI);
#pragma unroll
    for (int m = 0; m < 4; m++) {
        float z = zacc[m];
#pragma unroll
        for (int o = 1; o < 16; o <<= 1)
            z += __shfl_xor_sync(0xFFFFFFFFu, z, o);
        if (tx == 0) zr[ty + 16 * m] = z;
    }
    __syncthreads();
    if (tid < 64) {
        float z = zr[tid];
        zi[tid] = (z > 0.f) ? (1.f / z) : 0.f;
    }
    __syncthreads();

    float* outB = out + ((size_t)(b * NNODE + i0)) * DIM;
#pragma unroll
    for (int mt = 0; mt < 2; mt++) {
        const int r0 = warpM * 32 + mt * 16 + (lane >> 2);
        const int r1 = r0 + 8;
        const float z0 = zi[r0], z1 = zi[r1];
#pragma unroll
        for (int nt = 0; nt < 4; nt++) {
            const int c0 = warpN * 32 + nt * 8 + (lane & 3) * 2;
            *(float2*)(outB + (size_t)r0 * DIM + c0) =
                make_float2(acc[mt][nt][0] * z0, acc[mt][nt][1] * z0);
            *(float2*)(outB + (size_t)r1 * DIM + c0) =
                make_float2(acc[mt][nt][2] * z1, acc[mt][nt][3] * z1);
        }
    }
}

// ---------------------------------------------------------------------------
extern "C" void kernel_launch(void* const* d_in, const int* in_sizes, int n_in,
                              void* d_out, int out_size)
{
    const float* h   = (const float*)d_in[0];
    const int*   adj = (const int*)  d_in[1];
    const float* W   = (const float*)d_in[2];
    const float* a   = (const float*)d_in[3];
    float*       out = (float*)d_out;

    static int attr_set = 0;
    if (!attr_set) {
        cudaFuncSetAttribute(gat_wh_st, cudaFuncAttributeMaxDynamicSharedMemorySize, A_SMEM);
        cudaFuncSetAttribute(gat_fused, cudaFuncAttributeMaxDynamicSharedMemorySize, F_SMEM);
        attr_set = 1;
    }

    gat_wh_st<<<NROWS / 64, 256, A_SMEM>>>(h, W, a);
    gat_fused<<<dim3(NNODE / 64, BATCH), 256, F_SMEM>>>(adj, out);
}

// round 17
// speedup vs baseline: 2.3372x; 1.0370x over previous
#include <cuda_runtime.h>
#include <cuda_fp16.h>
#include <cstdint>

#define BATCH 8
#define NNODE 2048
#define DIM   128
#define NROWS (BATCH * NNODE)

__device__ float  g_u[NROWS], g_v[NROWS], g_p[NROWS], g_q[NROWS];
__device__ __half g_BH[NROWS * DIM];     // Wh fp16 rn [b][j][f]

// ---------------- helpers ----------------
__device__ __forceinline__ uint32_t smem_u32(const void* p) {
    uint32_t a;
    asm("{ .reg .u64 t; cvta.to.shared.u64 t, %1; cvt.u32.u64 %0, t; }" : "=r"(a) : "l"(p));
    return a;
}
__device__ __forceinline__ void ldsm_x4(uint32_t& r0, uint32_t& r1, uint32_t& r2, uint32_t& r3, uint32_t a) {
    asm volatile("ldmatrix.sync.aligned.m8n8.x4.shared.b16 {%0,%1,%2,%3}, [%4];"
                 : "=r"(r0), "=r"(r1), "=r"(r2), "=r"(r3) : "r"(a));
}
__device__ __forceinline__ void ldsm_x4t(uint32_t& r0, uint32_t& r1, uint32_t& r2, uint32_t& r3, uint32_t a) {
    asm volatile("ldmatrix.sync.aligned.m8n8.x4.trans.shared.b16 {%0,%1,%2,%3}, [%4];"
                 : "=r"(r0), "=r"(r1), "=r"(r2), "=r"(r3) : "r"(a));
}
__device__ __forceinline__ void mma16816(float* c, const uint32_t* a, uint32_t b0, uint32_t b1) {
    asm volatile(
        "mma.sync.aligned.m16n8k16.row.col.f32.f16.f16.f32 "
        "{%0,%1,%2,%3}, {%4,%5,%6,%7}, {%8,%9}, {%0,%1,%2,%3};"
        : "+f"(c[0]), "+f"(c[1]), "+f"(c[2]), "+f"(c[3])
        : "r"(a[0]), "r"(a[1]), "r"(a[2]), "r"(a[3]), "r"(b0), "r"(b1));
}
__device__ __forceinline__ void cp_async16(uint32_t dst, const void* src) {
    asm volatile("cp.async.cg.shared.global [%0], [%1], 16;" :: "r"(dst), "l"(src));
}
__device__ __forceinline__ uint32_t pack_f16x2(float lo, float hi) {   // lower<-lo, upper<-hi
    uint32_t r;
    asm("cvt.rn.f16x2.f32 %0, %1, %2;" : "=r"(r) : "f"(hi), "f"(lo));
    return r;
}
// streaming adj load: L2 evict-first via cache-hint policy (protect Wh/v/q)
__device__ __forceinline__ int4 ldg_stream(const int* p) {
    int4 v;
    asm volatile(
        "{\n\t.reg .b64 pol;\n\t"
        "createpolicy.fractional.L2::evict_first.b64 pol, 1.0;\n\t"
        "ld.global.nc.L2::cache_hint.v4.s32 {%0,%1,%2,%3}, [%4], pol;\n\t}"
        : "=r"(v.x), "=r"(v.y), "=r"(v.z), "=r"(v.w) : "l"(p));
    return v;
}

// ---------------------------------------------------------------------------
// K1: Wh = h @ W^T (hi/lo mma) + s,t + exp factors (measured 12.2-12.4 us)
// ---------------------------------------------------------------------------
#define A_AH   0
#define A_AL   16384
#define A_BH   32768
#define A_BL   65536
#define A_SRED 98304
#define A_SMEM 100352

__global__ void __launch_bounds__(256, 2) gat_wh_st(
    const float* __restrict__ h, const float* __restrict__ W,
    const float* __restrict__ a)
{
    extern __shared__ char sm[];
    const uint32_t sb = smem_u32(sm);
    const int tid = threadIdx.x, lane = tid & 31, wid = tid >> 5;
    const int row0 = blockIdx.x * 64;

#pragma unroll
    for (int c = 0; c < 8; c++) {
        int idx = tid + 256 * c;
        int r = idx >> 5, fq = idx & 31;
        float4 w = *(const float4*)(h + (size_t)(row0 + r) * 128 + fq * 4);
        __half h0 = __float2half_rn(w.x), h1 = __float2half_rn(w.y);
        __half h2 = __float2half_rn(w.z), h3 = __float2half_rn(w.w);
        float l0 = w.x - __half2float(h0), l1 = w.y - __half2float(h1);
        float l2 = w.z - __half2float(h2), l3 = w.w - __half2float(h3);
        uint32_t sw = (uint32_t)(r * 256 + ((fq * 8) ^ ((r & 7) << 4)));
        __half2 hA = __halves2half2(h0, h1), hB = __halves2half2(h2, h3);
        *(uint2*)(sm + A_AH + sw) = make_uint2(*(uint32_t*)&hA, *(uint32_t*)&hB);
        *(uint2*)(sm + A_AL + sw) = make_uint2(pack_f16x2(l0, l1), pack_f16x2(l2, l3));
    }
#pragma unroll
    for (int c = 0; c < 16; c++) {
        int idx = tid + 256 * c;
        int o = idx >> 5, fq = idx & 31;
        float4 w = *(const float4*)(W + (size_t)o * 128 + fq * 4);
        __half h0 = __float2half_rn(w.x), h1 = __float2half_rn(w.y);
        __half h2 = __float2half_rn(w.z), h3 = __float2half_rn(w.w);
        float l0 = w.x - __half2float(h0), l1 = w.y - __half2float(h1);
        float l2 = w.z - __half2float(h2), l3 = w.w - __half2float(h3);
        uint32_t sw = (uint32_t)(o * 256 + ((fq * 8) ^ ((o & 7) << 4)));
        __half2 hA = __halves2half2(h0, h1), hB = __halves2half2(h2, h3);
        *(uint2*)(sm + A_BH + sw) = make_uint2(*(uint32_t*)&hA, *(uint32_t*)&hB);
        *(uint2*)(sm + A_BL + sw) = make_uint2(pack_f16x2(l0, l1), pack_f16x2(l2, l3));
    }
    __syncthreads();

    const int warpM = wid >> 2, warpN = wid & 3;
    const int l15 = lane & 15, l16 = lane >> 4;
    const uint32_t xorv = (uint32_t)((l15 & 7) << 4);

    float acc[2][4][4];
#pragma unroll
    for (int mt = 0; mt < 2; mt++)
#pragma unroll
        for (int nt = 0; nt < 4; nt++)
#pragma unroll
            for (int e = 0; e < 4; e++) acc[mt][nt][e] = 0.f;

    uint32_t aRow[2];
#pragma unroll
    for (int mt = 0; mt < 2; mt++)
        aRow[mt] = (uint32_t)((warpM * 32 + mt * 16 + l15) * 256);

    const int bR = (lane >> 4) * 8 + (lane & 7);
    const uint32_t bKoff = (uint32_t)(((lane >> 3) & 1) * 16);
    const uint32_t bXor = (uint32_t)((lane & 7) << 4);

#pragma unroll
    for (int kk = 0; kk < 8; kk++) {
        const uint32_t aCol = ((uint32_t)(kk * 32 + l16 * 16)) ^ xorv;
        uint32_t aH[2][4], aL[2][4];
#pragma unroll
        for (int mt = 0; mt < 2; mt++) {
            ldsm_x4(aH[mt][0], aH[mt][1], aH[mt][2], aH[mt][3], sb + A_AH + aRow[mt] + aCol);
            ldsm_x4(aL[mt][0], aL[mt][1], aL[mt][2], aL[mt][3], sb + A_AL + aRow[mt] + aCol);
        }
        uint32_t bH[2][4], bL[2][4];
#pragma unroll
        for (int ng = 0; ng < 2; ng++) {
            int n = warpN * 32 + ng * 16 + bR;
            uint32_t addr = (uint32_t)(n * 256) + (((uint32_t)(kk * 32) + bKoff) ^ bXor);
            ldsm_x4(bH[ng][0], bH[ng][1], bH[ng][2], bH[ng][3], sb + A_BH + addr);
            ldsm_x4(bL[ng][0], bL[ng][1], bL[ng][2], bL[ng][3], sb + A_BL + addr);
        }
#pragma unroll
        for (int mt = 0; mt < 2; mt++)
#pragma unroll
            for (int nt = 0; nt < 4; nt++) {
                const int g = nt >> 1, hh = (nt & 1) * 2;
                mma16816(acc[mt][nt], aH[mt], bH[g][hh], bH[g][hh + 1]);
                mma16816(acc[mt][nt], aH[mt], bL[g][hh], bL[g][hh + 1]);
                mma16816(acc[mt][nt], aL[mt], bH[g][hh], bH[g][hh + 1]);
            }
    }

#pragma unroll
    for (int mt = 0; mt < 2; mt++) {
        const int r0 = row0 + warpM * 32 + mt * 16 + (lane >> 2);
        const int r1 = r0 + 8;
#pragma unroll
        for (int nt = 0; nt < 4; nt++) {
            const int c0 = warpN * 32 + nt * 8 + (lane & 3) * 2;
            __half h0 = __float2half_rn(acc[mt][nt][0]), h1 = __float2half_rn(acc[mt][nt][1]);
            __half h2 = __float2half_rn(acc[mt][nt][2]), h3 = __float2half_rn(acc[mt][nt][3]);
            __half2 p0 = __halves2half2(h0, h1), p1 = __halves2half2(h2, h3);
            *(uint32_t*)(g_BH + (size_t)r0 * 128 + c0) = *(uint32_t*)&p0;
            *(uint32_t*)(g_BH + (size_t)r1 * 128 + c0) = *(uint32_t*)&p1;
        }
    }

    float ps[2][2] = {{0.f,0.f},{0.f,0.f}}, pt[2][2] = {{0.f,0.f},{0.f,0.f}};
#pragma unroll
    for (int mt = 0; mt < 2; mt++)
#pragma unroll
        for (int nt = 0; nt < 4; nt++) {
            const int c0 = warpN * 32 + nt * 8 + (lane & 3) * 2;
            float2 av = *(const float2*)(a + c0);
            float2 dv = *(const float2*)(a + 128 + c0);
            ps[mt][0] += acc[mt][nt][0] * av.x + acc[mt][nt][1] * av.y;
            ps[mt][1] += acc[mt][nt][2] * av.x + acc[mt][nt][3] * av.y;
            pt[mt][0] += acc[mt][nt][0] * dv.x + acc[mt][nt][1] * dv.y;
            pt[mt][1] += acc[mt][nt][2] * dv.x + acc[mt][nt][3] * dv.y;
        }
#pragma unroll
    for (int o = 1; o < 4; o <<= 1) {
#pragma unroll
        for (int mt = 0; mt < 2; mt++) {
            ps[mt][0] += __shfl_xor_sync(0xFFFFFFFFu, ps[mt][0], o);
            ps[mt][1] += __shfl_xor_sync(0xFFFFFFFFu, ps[mt][1], o);
            pt[mt][0] += __shfl_xor_sync(0xFFFFFFFFu, pt[mt][0], o);
            pt[mt][1] += __shfl_xor_sync(0xFFFFFFFFu, pt[mt][1], o);
        }
    }
    float* sredS = (float*)(sm + A_SRED);
    float* sredT = (float*)(sm + A_SRED + 1024);
    if ((lane & 3) == 0) {
#pragma unroll
        for (int mt = 0; mt < 2; mt++) {
            int rl = warpM * 32 + mt * 16 + (lane >> 2);
            sredS[rl * 4 + warpN] = ps[mt][0];
            sredS[(rl + 8) * 4 + warpN] = ps[mt][1];
            sredT[rl * 4 + warpN] = pt[mt][0];
            sredT[(rl + 8) * 4 + warpN] = pt[mt][1];
        }
    }
    __syncthreads();
    if (tid < 64) {
        float s = sredS[tid*4] + sredS[tid*4+1] + sredS[tid*4+2] + sredS[tid*4+3];
        float t = sredT[tid*4] + sredT[tid*4+1] + sredT[tid*4+2] + sredT[tid*4+3];
        int row = row0 + tid;
        g_u[row] = __expf(s);   g_p[row] = __expf(0.2f * s);
        g_v[row] = __expf(t);   g_q[row] = __expf(0.2f * t);
    }
}

// ---------------------------------------------------------------------------
// K4: fused — R15 winner + adj evict_first(policy) + adj prefetch at kk==0.
// ---------------------------------------------------------------------------
#define TK 64
#define F_P(bu)  ((bu) * 8192)
#define F_B(bu)  (16384 + (bu) * 16384)
#define F_V      49152
#define F_Q      57344
#define F_ZR     65536
#define F_ZI     65792
#define F_SMEM   66048

__global__ void __launch_bounds__(256, 2) gat_fused(
    const int* __restrict__ adj, float* __restrict__ out)
{
    extern __shared__ char sm[];
    const uint32_t sb = smem_u32(sm);
    const int tid = threadIdx.x, lane = tid & 31, wid = tid >> 5;
    const int b = blockIdx.y, i0 = blockIdx.x * 64;
    const int tx = tid & 15, ty = tid >> 4;

    const __half* BHg = g_BH + (size_t)b * NNODE * DIM;

    float u_r[4], p_r[4];
    const int* adjRow[4];
#pragma unroll
    for (int m = 0; m < 4; m++) {
        int il = ty + 16 * m;
        u_r[m] = g_u[b * NNODE + i0 + il];
        p_r[m] = g_p[b * NNODE + i0 + il];
        adjRow[m] = adj + ((size_t)(b * NNODE + i0 + il)) * NNODE + 4 * tx;
    }

    // prologue: v,q (16KB) + B(0) via cp.async
#pragma unroll
    for (int c = 0; c < 2; c++) {
        int idx = tid + 256 * c;
        cp_async16(sb + F_V + idx * 16, g_v + b * NNODE + idx * 4);
        cp_async16(sb + F_Q + idx * 16, g_q + b * NNODE + idx * 4);
    }
#pragma unroll
    for (int c2 = 0; c2 < 4; c2++) {
        int c = tid + 256 * c2;
        int row = c >> 4, col = c & 15;
        uint32_t sw = (uint32_t)(row * 256 + ((col * 16) ^ ((row & 7) << 4)));
        cp_async16(sb + F_B(0) + sw, BHg + (size_t)row * DIM + col * 8);
    }
    asm volatile("cp.async.commit_group;" ::: "memory");
    asm volatile("cp.async.wait_group 0;" ::: "memory");
    __syncthreads();

    float zacc[4] = {0.f, 0.f, 0.f, 0.f};

    // construct P(0)
    {
        float4 v4 = *(const float4*)(sm + F_V + 16 * tx);
        float4 q4 = *(const float4*)(sm + F_Q + 16 * tx);
        char* P = sm + F_P(0);
#pragma unroll
        for (int m = 0; m < 4; m++) {
            const int row = ty + 16 * m;
            int4 a4 = ldg_stream(adjRow[m]);
            const float u = u_r[m], p = p_r[m];
            uint32_t w0 = __float_as_uint(fmaxf(u * v4.x, p * q4.x)) & (uint32_t)(-a4.x);
            uint32_t w1 = __float_as_uint(fmaxf(u * v4.y, p * q4.y)) & (uint32_t)(-a4.y);
            uint32_t w2 = __float_as_uint(fmaxf(u * v4.z, p * q4.z)) & (uint32_t)(-a4.z);
            uint32_t w3 = __float_as_uint(fmaxf(u * v4.w, p * q4.w)) & (uint32_t)(-a4.w);
            float f0 = __uint_as_float(w0), f1 = __uint_as_float(w1);
            float f2 = __uint_as_float(w2), f3 = __uint_as_float(w3);
            zacc[m] += (f0 + f1) + (f2 + f3);
            *(uint2*)(P + row * 128 + ((tx * 8) ^ ((row & 7) << 4))) =
                make_uint2(pack_f16x2(f0, f1), pack_f16x2(f2, f3));
        }
    }

    int4 aN[4];
#pragma unroll
    for (int m = 0; m < 4; m++) aN[m] = ldg_stream(adjRow[m] + TK);

    float acc[2][4][4];
#pragma unroll
    for (int mt = 0; mt < 2; mt++)
#pragma unroll
        for (int nt = 0; nt < 4; nt++)
#pragma unroll
            for (int e = 0; e < 4; e++) acc[mt][nt][e] = 0.f;

    const int warpM = wid >> 2, warpN = wid & 3;
    const int l15 = lane & 15, l16 = lane >> 4;
    const uint32_t xorv = (uint32_t)((l15 & 7) << 4);
    uint32_t aRow[2];
#pragma unroll
    for (int mt = 0; mt < 2; mt++)
        aRow[mt] = (uint32_t)((warpM * 32 + mt * 16 + l15) * 128);
    uint32_t bCol[2];
#pragma unroll
    for (int ng = 0; ng < 2; ng++)
        bCol[ng] = ((uint32_t)((warpN * 32 + ng * 16 + l16 * 8) * 2)) ^ xorv;
    const uint32_t bRow0 = (uint32_t)(l15 * 256);

    __syncthreads();

    for (int kt = 0; kt < NNODE / TK; ++kt) {
        const int cb = kt & 1, pb = cb ^ 1;

        if (kt < 31) {
            const int j1 = (kt + 1) * TK;
#pragma unroll
            for (int c2 = 0; c2 < 4; c2++) {
                int c = tid + 256 * c2;
                int row = c >> 4, col = c & 15;
                uint32_t sw = (uint32_t)(row * 256 + ((col * 16) ^ ((row & 7) << 4)));
                cp_async16(sb + F_B(pb) + sw, BHg + (size_t)(j1 + row) * DIM + col * 8);
            }
        }
        asm volatile("cp.async.commit_group;" ::: "memory");

        const uint32_t Pb = sb + F_P(cb), Bb = sb + F_B(cb);
#pragma unroll
        for (int kk = 0; kk < 4; ++kk) {
            const uint32_t aCol = ((uint32_t)(kk * 32 + l16 * 16)) ^ xorv;
            uint32_t aH[2][4];
#pragma unroll
            for (int mt = 0; mt < 2; mt++)
                ldsm_x4(aH[mt][0], aH[mt][1], aH[mt][2], aH[mt][3], Pb + aRow[mt] + aCol);
            const uint32_t bRow = bRow0 + (uint32_t)(kk * 4096);
            uint32_t bH[2][4];
#pragma unroll
            for (int ng = 0; ng < 2; ng++)
                ldsm_x4t(bH[ng][0], bH[ng][1], bH[ng][2], bH[ng][3], Bb + bRow + bCol[ng]);
#pragma unroll
            for (int mt = 0; mt < 2; mt++)
#pragma unroll
                for (int nt = 0; nt < 4; nt++) {
                    const int g = nt >> 1, hh = (nt & 1) * 2;
                    mma16816(acc[mt][nt], aH[mt], bH[g][hh], bH[g][hh + 1]);
                }

            if (kk == 0 && kt < 31) {
                const int jn = (kt + 1) * TK + 4 * tx;
                float4 v4 = *(const float4*)(sm + F_V + jn * 4);
                float4 q4 = *(const float4*)(sm + F_Q + jn * 4);
                char* P = sm + F_P(pb);
#pragma unroll
                for (int m = 0; m < 4; m++) {
                    const int row = ty + 16 * m;
                    const int4 a4 = aN[m];
                    const float u = u_r[m], p = p_r[m];
                    uint32_t w0 = __float_as_uint(fmaxf(u * v4.x, p * q4.x)) & (uint32_t)(-a4.x);
                    uint32_t w1 = __float_as_uint(fmaxf(u * v4.y, p * q4.y)) & (uint32_t)(-a4.y);
                    uint32_t w2 = __float_as_uint(fmaxf(u * v4.z, p * q4.z)) & (uint32_t)(-a4.z);
                    uint32_t w3 = __float_as_uint(fmaxf(u * v4.w, p * q4.w)) & (uint32_t)(-a4.w);
                    float f0 = __uint_as_float(w0), f1 = __uint_as_float(w1);
                    float f2 = __uint_as_float(w2), f3 = __uint_as_float(w3);
                    zacc[m] += (f0 + f1) + (f2 + f3);
                    *(uint2*)(P + row * 128 + ((tx * 8) ^ ((row & 7) << 4))) =
                        make_uint2(pack_f16x2(f0, f1), pack_f16x2(f2, f3));
                }
                if (kt < 30) {
                    const int j2 = (kt + 2) * TK;
#pragma unroll
                    for (int m = 0; m < 4; m++)
                        aN[m] = ldg_stream(adjRow[m] + j2);
                }
            }
        }
        asm volatile("cp.async.wait_group 0;" ::: "memory");
        __syncthreads();
    }

    // Z reduction and normalize
    float* zr = (float*)(sm + F_ZR);
    float* zi = (float*)(sm + F_ZI);
#pragma unroll
    for (int m = 0; m < 4; m++) {
        float z = zacc[m];
#pragma unroll
        for (int o = 1; o < 16; o <<= 1)
            z += __shfl_xor_sync(0xFFFFFFFFu, z, o);
        if (tx == 0) zr[ty + 16 * m] = z;
    }
    __syncthreads();
    if (tid < 64) {
        float z = zr[tid];
        zi[tid] = (z > 0.f) ? (1.f / z) : 0.f;
    }
    __syncthreads();

    float* outB = out + ((size_t)(b * NNODE + i0)) * DIM;
#pragma unroll
    for (int mt = 0; mt < 2; mt++) {
        const int r0 = warpM * 32 + mt * 16 + (lane >> 2);
        const int r1 = r0 + 8;
        const float z0 = zi[r0], z1 = zi[r1];
#pragma unroll
        for (int nt = 0; nt < 4; nt++) {
            const int c0 = warpN * 32 + nt * 8 + (lane & 3) * 2;
            *(float2*)(outB + (size_t)r0 * DIM + c0) =
                make_float2(acc[mt][nt][0] * z0, acc[mt][nt][1] * z0);
            *(float2*)(outB + (size_t)r1 * DIM + c0) =
                make_float2(acc[mt][nt][2] * z1, acc[mt][nt][3] * z1);
        }
    }
}

// ---------------------------------------------------------------------------
extern "C" void kernel_launch(void* const* d_in, const int* in_sizes, int n_in,
                              void* d_out, int out_size)
{
    const float* h   = (const float*)d_in[0];
    const int*   adj = (const int*)  d_in[1];
    const float* W   = (const float*)d_in[2];
    const float* a   = (const float*)d_in[3];
    float*       out = (float*)d_out;

    static int attr_set = 0;
    if (!attr_set) {
        cudaFuncSetAttribute(gat_wh_st, cudaFuncAttributeMaxDynamicSharedMemorySize, A_SMEM);
        cudaFuncSetAttribute(gat_fused, cudaFuncAttributeMaxDynamicSharedMemorySize, F_SMEM);
        attr_set = 1;
    }

    gat_wh_st<<<NROWS / 64, 256, A_SMEM>>>(h, W, a);
    gat_fused<<<dim3(NNODE / 64, BATCH), 256, F_SMEM>>>(adj, out);
}